// round 1
// baseline (speedup 1.0000x reference)
#include <cuda_runtime.h>
#include <math.h>
#include <stdint.h>

#define BN   65536      // B*N total nodes
#define NPB  16384      // nodes per batch
#define NE   262144     // total edges (B*E)

// ---------------- device scratch (no allocations allowed) ----------------
__device__ __align__(16) float g_P [(size_t)BN * 128];   // [P1 | P2] per node
__device__ __align__(16) float g_dh[(size_t)BN * 64];    // scattered m_ij
__device__ __align__(16) float g_dx[(size_t)BN * 3];     // scattered delta_x
__device__ __align__(16) float g_t [(size_t)BN * 128];   // silu(h_input @ ph_w1 + b1)

__device__ __forceinline__ float silu_f(float v) {
    return v * (1.0f / (1.0f + __expf(-v)));
}

// ---------------- zero the scatter accumulators ----------------
__global__ void zero_kernel() {
    const size_t n1 = (size_t)BN * 64;
    const size_t n2 = (size_t)BN * 3;
    const size_t total = n1 + n2;
    for (size_t i = (size_t)blockIdx.x * blockDim.x + threadIdx.x; i < total;
         i += (size_t)gridDim.x * blockDim.x) {
        if (i < n1) g_dh[i] = 0.f;
        else        g_dx[i - n1] = 0.f;
    }
}

// ---------------- generic 128x128-tile SGEMM, 256 threads, 8x8/thread ----
// MODE 0: C=g_P      : A=h (K=128),        B=pe_w1 gathered [W1a|W1b], no bias
// MODE 1: C=g_t      : A=[h|g_dh] (K=192), B=ph_w1, bias=ph_b1, silu
// MODE 2: C=Cout     : A=g_t (K=128),      B=ph_w2, bias=ph_b2, +h residual
template<int MODE, int KTOT>
__global__ __launch_bounds__(256) void gemm_kernel(
    const float* __restrict__ A,     // h (modes 0,1); h for residual (mode 2)
    const float* __restrict__ Bm,
    const float* __restrict__ bias,
    float* __restrict__ Cout)
{
    __shared__ float sA[8][132];
    __shared__ float sB[8][128];
    const int tid = threadIdx.x;
    const int tx = tid & 15, ty = tid >> 4;
    const int m0 = blockIdx.x * 128;

    float acc[8][8];
#pragma unroll
    for (int i = 0; i < 8; i++)
#pragma unroll
        for (int j = 0; j < 8; j++) acc[i][j] = 0.f;

    const int arow = m0 + (tid >> 1);
    const int akk  = (tid & 1) * 4;
    const int bkk  = tid >> 5;
    const int bj   = (tid & 31) * 4;

    for (int k0 = 0; k0 < KTOT; k0 += 8) {
        // global loads for this k-slice
        float4 av;
        {
            const int f = k0 + akk;
            if (MODE == 2) {
                av = *(const float4*)(g_t + (size_t)arow * 128 + f);
            } else if (MODE == 1) {
                if (f < 128) av = *(const float4*)(A   + (size_t)arow * 128 + f);
                else         av = *(const float4*)(g_dh + (size_t)arow * 64 + (f - 128));
            } else {
                av = *(const float4*)(A + (size_t)arow * 128 + f);
            }
        }
        float4 bv;
        {
            const int fb = k0 + bkk;
            if (MODE == 0) {
                if (bj < 64) bv = *(const float4*)(Bm + (size_t)fb * 64 + bj);
                else         bv = *(const float4*)(Bm + (size_t)(128 + fb) * 64 + (bj - 64));
            } else {
                bv = *(const float4*)(Bm + (size_t)fb * 128 + bj);
            }
        }
        __syncthreads();
        const int lr = tid >> 1;
        sA[akk + 0][lr] = av.x; sA[akk + 1][lr] = av.y;
        sA[akk + 2][lr] = av.z; sA[akk + 3][lr] = av.w;
        *(float4*)&sB[bkk][bj] = bv;
        __syncthreads();

#pragma unroll
        for (int kk = 0; kk < 8; kk++) {
            float a[8], b[8];
            *(float4*)&a[0] = *(const float4*)&sA[kk][ty * 8];
            *(float4*)&a[4] = *(const float4*)&sA[kk][ty * 8 + 4];
            *(float4*)&b[0] = *(const float4*)&sB[kk][tx * 8];
            *(float4*)&b[4] = *(const float4*)&sB[kk][tx * 8 + 4];
#pragma unroll
            for (int i = 0; i < 8; i++)
#pragma unroll
                for (int j = 0; j < 8; j++)
                    acc[i][j] = fmaf(a[i], b[j], acc[i][j]);
        }
    }

    // epilogue
#pragma unroll
    for (int i = 0; i < 8; i++) {
        const int row = m0 + ty * 8 + i;
        const size_t base = (size_t)row * 128 + tx * 8;
#pragma unroll
        for (int q = 0; q < 2; q++) {
            float v0 = acc[i][q * 4 + 0], v1 = acc[i][q * 4 + 1];
            float v2 = acc[i][q * 4 + 2], v3 = acc[i][q * 4 + 3];
            if (MODE == 1) {
                const float4 bb = *(const float4*)(bias + tx * 8 + q * 4);
                v0 = silu_f(v0 + bb.x); v1 = silu_f(v1 + bb.y);
                v2 = silu_f(v2 + bb.z); v3 = silu_f(v3 + bb.w);
            }
            if (MODE == 2) {
                const float4 bb = *(const float4*)(bias + tx * 8 + q * 4);
                const float4 hh = *(const float4*)(A + base + q * 4);
                v0 += bb.x + hh.x; v1 += bb.y + hh.y;
                v2 += bb.z + hh.z; v3 += bb.w + hh.w;
            }
            float4 ov = make_float4(v0, v1, v2, v3);
            if (MODE == 0)      *(float4*)(g_P  + base + q * 4) = ov;
            else if (MODE == 1) *(float4*)(g_t  + base + q * 4) = ov;
            else                *(float4*)(Cout + base + q * 4) = ov;
        }
    }
}

// ---------------- edge kernel: 128 edges/block, 256 threads ----------------
// m   = silu(P1[src] + P2[dst] + dist2*W1[256] + b1)       (per edge, 64)
// m2  = silu(m @ W2 + b2)                                   (GEMM2, K=64)
// m_x = m2 . px_w ; scatter m2 -> g_dh[src], m_x*dir -> g_dx[src]
__global__ __launch_bounds__(256) void edge_kernel(
    const float* __restrict__ x,
    const int*   __restrict__ edges,
    const float* __restrict__ W1,
    const float* __restrict__ b1,
    const float* __restrict__ W2,
    const float* __restrict__ b2,
    const float* __restrict__ pxw)
{
    extern __shared__ float dyn[];
    float* sW2 = dyn;            // 64*64
    float* sM  = dyn + 4096;     // 128*65 (padded)

    __shared__ int   sSrc[128], sDst[128];
    __shared__ float sD2[128];
    __shared__ float sDirx[128], sDiry[128], sDirz[128];
    __shared__ float sB1[64], sB2[64], sPx[64], sW1r[64];

    const int tid = threadIdx.x;
    const int tx = tid & 15, ty = tid >> 4;
    const int e0 = blockIdx.x * 128;

    if (tid < 128) {
        const int eg = e0 + tid;
        const int b  = eg >> 16;                 // E per batch = 65536
        const int2 sd = ((const int2*)edges)[eg];
        const int gi = b * NPB + sd.x;
        const int gj = b * NPB + sd.y;
        sSrc[tid] = gi; sDst[tid] = gj;
        const float xi0 = x[(size_t)gi * 3 + 0], xi1 = x[(size_t)gi * 3 + 1], xi2 = x[(size_t)gi * 3 + 2];
        const float xj0 = x[(size_t)gj * 3 + 0], xj1 = x[(size_t)gj * 3 + 1], xj2 = x[(size_t)gj * 3 + 2];
        const float d0 = xi0 - xj0, d1 = xi1 - xj1, d2c = xi2 - xj2;
        float d2 = d0 * d0 + d1 * d1 + d2c * d2c;
        d2 = fmaxf(d2, 1e-12f);
        sD2[tid] = d2;
        const float inv = 1.0f / (sqrtf(d2) + 1e-8f);
        sDirx[tid] = d0 * inv; sDiry[tid] = d1 * inv; sDirz[tid] = d2c * inv;
    }
    if (tid < 64) {
        sB1[tid] = b1[tid];
        sB2[tid] = b2[tid];
        sPx[tid] = pxw[tid];
        sW1r[tid] = W1[256 * 64 + tid];
    }
#pragma unroll
    for (int i = tid; i < 1024; i += 256)
        *(float4*)&sW2[i * 4] = *(const float4*)&W2[i * 4];
    __syncthreads();

    // m tile (silu applied); coalesced gathers from g_P
#pragma unroll 4
    for (int it = 0; it < 32; ++it) {
        const int idx = it * 256 + tid;
        const int e = idx >> 6, k = idx & 63;
        float v = g_P[(size_t)sSrc[e] * 128 + k]
                + g_P[(size_t)sDst[e] * 128 + 64 + k]
                + sD2[e] * sW1r[k] + sB1[k];
        sM[e * 65 + k] = silu_f(v);
    }
    __syncthreads();

    // GEMM2: 128 edges x 64 outs, K=64; each thread 8 edges x 4 outs
    float acc[8][4];
#pragma unroll
    for (int i = 0; i < 8; i++)
#pragma unroll
        for (int j = 0; j < 4; j++) acc[i][j] = 0.f;

#pragma unroll 4
    for (int kk = 0; kk < 64; ++kk) {
        const float4 bv = *(const float4*)&sW2[kk * 64 + tx * 4];
#pragma unroll
        for (int i = 0; i < 8; i++) {
            const float a = sM[(ty * 8 + i) * 65 + kk];
            acc[i][0] = fmaf(a, bv.x, acc[i][0]);
            acc[i][1] = fmaf(a, bv.y, acc[i][1]);
            acc[i][2] = fmaf(a, bv.z, acc[i][2]);
            acc[i][3] = fmaf(a, bv.w, acc[i][3]);
        }
    }

    const float4 pxv = *(const float4*)&sPx[tx * 4];
    const float4 b2v = *(const float4*)&sB2[tx * 4];
#pragma unroll
    for (int i = 0; i < 8; i++) {
        const int e = ty * 8 + i;
        const int node = sSrc[e];
        const float v0 = silu_f(acc[i][0] + b2v.x);
        const float v1 = silu_f(acc[i][1] + b2v.y);
        const float v2 = silu_f(acc[i][2] + b2v.z);
        const float v3 = silu_f(acc[i][3] + b2v.w);
        float* dst = &g_dh[(size_t)node * 64 + tx * 4];
        atomicAdd(dst + 0, v0);
        atomicAdd(dst + 1, v1);
        atomicAdd(dst + 2, v2);
        atomicAdd(dst + 3, v3);
        float part = v0 * pxv.x + v1 * pxv.y + v2 * pxv.z + v3 * pxv.w;
#pragma unroll
        for (int o = 8; o >= 1; o >>= 1)
            part += __shfl_xor_sync(0xffffffffu, part, o);
        if (tx == 0) {
            atomicAdd(&g_dx[(size_t)node * 3 + 0], part * sDirx[e]);
            atomicAdd(&g_dx[(size_t)node * 3 + 1], part * sDiry[e]);
            atomicAdd(&g_dx[(size_t)node * 3 + 2], part * sDirz[e]);
        }
    }
}

// ---------------- x_new = x + delta_x ----------------
__global__ void xout_kernel(const float* __restrict__ x, float* __restrict__ out) {
    const int i = blockIdx.x * blockDim.x + threadIdx.x;
    if (i < BN * 3) out[i] = x[i] + g_dx[i];
}

// ---------------- launch ----------------
extern "C" void kernel_launch(void* const* d_in, const int* in_sizes, int n_in,
                              void* d_out, int out_size) {
    const float* x   = (const float*)d_in[0];
    const float* h   = (const float*)d_in[1];
    const int*   ei  = (const int*)d_in[2];
    const float* pw1 = (const float*)d_in[3];
    const float* pb1 = (const float*)d_in[4];
    const float* pw2 = (const float*)d_in[5];
    const float* pb2 = (const float*)d_in[6];
    const float* pxw = (const float*)d_in[7];
    const float* hw1 = (const float*)d_in[8];
    const float* hb1 = (const float*)d_in[9];
    const float* hw2 = (const float*)d_in[10];
    const float* hb2 = (const float*)d_in[11];

    float* out   = (float*)d_out;
    float* out_x = out;                      // (B,N,3) flattened first
    float* out_h = out + (size_t)BN * 3;     // then (B,N,128)

    const int EDGE_SMEM = (4096 + 128 * 65) * (int)sizeof(float);  // 49664 B
    cudaFuncSetAttribute(edge_kernel, cudaFuncAttributeMaxDynamicSharedMemorySize, EDGE_SMEM);

    zero_kernel<<<512, 256>>>();
    gemm_kernel<0, 128><<<BN / 128, 256>>>(h, pw1, nullptr, nullptr);          // g_P
    edge_kernel<<<NE / 128, 256, EDGE_SMEM>>>(x, ei, pw1, pb1, pw2, pb2, pxw); // g_dh, g_dx
    gemm_kernel<1, 192><<<BN / 128, 256>>>(h, hw1, hb1, nullptr);              // g_t
    gemm_kernel<2, 128><<<BN / 128, 256>>>(h, hw2, hb2, out_h);                // h_new
    xout_kernel<<<(BN * 3 + 255) / 256, 256>>>(x, out_x);                      // x_new
}

// round 2
// speedup vs baseline: 1.8252x; 1.8252x over previous
#include <cuda_runtime.h>
#include <math.h>
#include <stdint.h>

#define BN   65536      // B*N total nodes
#define NPB  16384      // nodes per batch
#define NE   262144     // total edges (B*E)

// ---------------- device scratch (no allocations allowed) ----------------
__device__ __align__(16) float g_P [(size_t)BN * 128];   // [P1 | P2] per node
__device__ __align__(16) float g_dh[(size_t)BN * 64];    // scattered m_ij
__device__ __align__(16) float g_dx[(size_t)BN * 3];     // scattered delta_x
__device__ __align__(16) float g_t [(size_t)BN * 128];   // silu(h_input @ ph_w1 + b1)

__device__ __forceinline__ float silu_f(float v) {
    return v * (1.0f / (1.0f + __expf(-v)));
}

__device__ __forceinline__ uint32_t f2tf32(float f) {
    uint32_t r;
    asm("cvt.rna.tf32.f32 %0, %1;" : "=r"(r) : "f"(f));
    return r;
}

__device__ __forceinline__ void mma_tf32(float* c, const uint32_t* a, const uint32_t* b) {
    asm volatile("mma.sync.aligned.m16n8k8.row.col.f32.tf32.tf32.f32 "
        "{%0,%1,%2,%3}, {%4,%5,%6,%7}, {%8,%9}, {%0,%1,%2,%3};"
        : "+f"(c[0]), "+f"(c[1]), "+f"(c[2]), "+f"(c[3])
        : "r"(a[0]), "r"(a[1]), "r"(a[2]), "r"(a[3]), "r"(b[0]), "r"(b[1]));
}

// ---------------- zero the scatter accumulators ----------------
__global__ void zero_kernel() {
    float4 z = make_float4(0.f, 0.f, 0.f, 0.f);
    const size_t n1 = (size_t)BN * 16;       // g_dh in float4
    const size_t n2 = (size_t)BN * 3 / 4;    // g_dx in float4 (divisible)
    const size_t total = n1 + n2;
    for (size_t i = (size_t)blockIdx.x * blockDim.x + threadIdx.x; i < total;
         i += (size_t)gridDim.x * blockDim.x) {
        if (i < n1) ((float4*)g_dh)[i] = z;
        else        ((float4*)g_dx)[i - n1] = z;
    }
}

// ---------------- tf32 tensor-core GEMM, 128x128 tile, 256 threads ----------
// MODE 0: C=g_P : A=h (K=128),        B=pe_w1 split [W1a|W1b], no bias
// MODE 1: C=g_t : A=[h|g_dh] (K=192), B=ph_w1, bias=ph_b1, silu
// MODE 2: C=out : A=g_t (K=128),      B=ph_w2, bias=ph_b2, +h residual (A param = h)
template<int MODE, int KTOT>
__global__ __launch_bounds__(256) void gemm_tc(
    const float* __restrict__ A,
    const float* __restrict__ Bm,
    const float* __restrict__ bias,
    float* __restrict__ Cout)
{
    __shared__ uint32_t sA[128][36];   // [m][k], pad 4 -> conflict-free
    __shared__ uint32_t sB[32][132];   // [k][n], pad 4

    const int tid  = threadIdx.x;
    const int lane = tid & 31, warp = tid >> 5;
    const int wm = warp & 3, wn = warp >> 2;          // 4 warps M x 2 warps N
    const int m0 = blockIdx.x * 128;
    const int gq = lane >> 2, tq = lane & 3;

    float acc[2][8][4];
#pragma unroll
    for (int i = 0; i < 2; i++)
#pragma unroll
        for (int j = 0; j < 8; j++)
#pragma unroll
            for (int q = 0; q < 4; q++) acc[i][j][q] = 0.f;

    for (int k0 = 0; k0 < KTOT; k0 += 32) {
        // ---- load A chunk 128x32 ----
#pragma unroll
        for (int i = 0; i < 4; i++) {
            const int lin = i * 256 + tid;
            const int m = lin >> 3, kq = lin & 7;
            const int f = k0 + kq * 4;
            float4 v;
            if (MODE == 1) {
                if (f < 128) v = *(const float4*)(A    + (size_t)(m0 + m) * 128 + f);
                else         v = *(const float4*)(g_dh + (size_t)(m0 + m) * 64 + (f - 128));
            } else if (MODE == 2) {
                v = *(const float4*)(g_t + (size_t)(m0 + m) * 128 + f);
            } else {
                v = *(const float4*)(A + (size_t)(m0 + m) * 128 + f);
            }
            sA[m][kq * 4 + 0] = f2tf32(v.x);
            sA[m][kq * 4 + 1] = f2tf32(v.y);
            sA[m][kq * 4 + 2] = f2tf32(v.z);
            sA[m][kq * 4 + 3] = f2tf32(v.w);
        }
        // ---- load B chunk 32x128 ----
#pragma unroll
        for (int i = 0; i < 4; i++) {
            const int lin = i * 256 + tid;
            const int k = lin >> 5, nq = lin & 31;
            float4 v;
            if (MODE == 0) {
                if (nq < 16) v = *(const float4*)(Bm + (size_t)(k0 + k) * 64 + nq * 4);
                else         v = *(const float4*)(Bm + (size_t)(128 + k0 + k) * 64 + (nq - 16) * 4);
            } else {
                v = *(const float4*)(Bm + (size_t)(k0 + k) * 128 + nq * 4);
            }
            sB[k][nq * 4 + 0] = f2tf32(v.x);
            sB[k][nq * 4 + 1] = f2tf32(v.y);
            sB[k][nq * 4 + 2] = f2tf32(v.z);
            sB[k][nq * 4 + 3] = f2tf32(v.w);
        }
        __syncthreads();

#pragma unroll
        for (int ks = 0; ks < 4; ks++) {
            const int kb = ks * 8;
            uint32_t af[2][4], bf[8][2];
#pragma unroll
            for (int i = 0; i < 2; i++) {
                const int r = wm * 32 + i * 16 + gq;
                const int c = kb + tq;
                af[i][0] = sA[r][c];     af[i][1] = sA[r + 8][c];
                af[i][2] = sA[r][c + 4]; af[i][3] = sA[r + 8][c + 4];
            }
#pragma unroll
            for (int j = 0; j < 8; j++) {
                const int c = wn * 64 + j * 8 + gq;
                bf[j][0] = sB[kb + tq][c];
                bf[j][1] = sB[kb + tq + 4][c];
            }
#pragma unroll
            for (int i = 0; i < 2; i++)
#pragma unroll
                for (int j = 0; j < 8; j++)
                    mma_tf32(acc[i][j], af[i], bf[j]);
        }
        __syncthreads();
    }

    // ---- epilogue ----
#pragma unroll
    for (int i = 0; i < 2; i++) {
        const int rbase = m0 + wm * 32 + i * 16 + gq;
#pragma unroll
        for (int j = 0; j < 8; j++) {
            const int c = wn * 64 + j * 8 + tq * 2;
#pragma unroll
            for (int h2 = 0; h2 < 2; h2++) {
                const int r = rbase + h2 * 8;
                float v0 = acc[i][j][h2 * 2 + 0];
                float v1 = acc[i][j][h2 * 2 + 1];
                const size_t base = (size_t)r * 128 + c;
                if (MODE == 0) {
                    *(float2*)(g_P + base) = make_float2(v0, v1);
                } else if (MODE == 1) {
                    v0 = silu_f(v0 + __ldg(bias + c));
                    v1 = silu_f(v1 + __ldg(bias + c + 1));
                    *(float2*)(g_t + base) = make_float2(v0, v1);
                } else {
                    const float2 hh = *(const float2*)(A + base);
                    v0 += __ldg(bias + c) + hh.x;
                    v1 += __ldg(bias + c + 1) + hh.y;
                    *(float2*)(Cout + base) = make_float2(v0, v1);
                }
            }
        }
    }
}

// ---------------- edge kernel: 128 edges/block, 256 threads, tf32 GEMM2 ----
__global__ __launch_bounds__(256) void edge_kernel(
    const float* __restrict__ x,
    const int*   __restrict__ edges,
    const float* __restrict__ W1,
    const float* __restrict__ b1,
    const float* __restrict__ W2,
    const float* __restrict__ b2,
    const float* __restrict__ pxw)
{
    extern __shared__ uint32_t dyn[];
    uint32_t* sW2 = dyn;                 // [64][68] tf32
    uint32_t* sM  = dyn + 64 * 68;       // [128][68] tf32 (silu(m))

    __shared__ int   sSrc[128];
    __shared__ float sD2[128];
    __shared__ float sDirx[128], sDiry[128], sDirz[128];
    __shared__ float sB1[64], sB2[64], sPx[64], sW1r[64];

    const int tid  = threadIdx.x;
    const int lane = tid & 31, warp = tid >> 5;
    const int gq = lane >> 2, tq = lane & 3;
    const int e0 = blockIdx.x * 128;

    __shared__ int sDst[128];

    if (tid < 128) {
        const int eg = e0 + tid;
        const int b  = eg >> 16;                 // E per batch = 65536
        const int2 sd = ((const int2*)edges)[eg];
        const int gi = b * NPB + sd.x;
        const int gj = b * NPB + sd.y;
        sSrc[tid] = gi; sDst[tid] = gj;
        const float xi0 = x[(size_t)gi * 3 + 0], xi1 = x[(size_t)gi * 3 + 1], xi2 = x[(size_t)gi * 3 + 2];
        const float xj0 = x[(size_t)gj * 3 + 0], xj1 = x[(size_t)gj * 3 + 1], xj2 = x[(size_t)gj * 3 + 2];
        const float d0 = xi0 - xj0, d1 = xi1 - xj1, d2c = xi2 - xj2;
        float d2 = d0 * d0 + d1 * d1 + d2c * d2c;
        d2 = fmaxf(d2, 1e-12f);
        sD2[tid] = d2;
        const float inv = 1.0f / (sqrtf(d2) + 1e-8f);
        sDirx[tid] = d0 * inv; sDiry[tid] = d1 * inv; sDirz[tid] = d2c * inv;
    }
    if (tid < 64) {
        sB1[tid] = b1[tid];
        sB2[tid] = b2[tid];
        sPx[tid] = pxw[tid];
        sW1r[tid] = W1[256 * 64 + tid];
    }
    // W2 (64x64) -> tf32 smem, [k][68]
#pragma unroll
    for (int i = 0; i < 4; i++) {
        const int lin = i * 256 + tid;
        const int k = lin >> 4, nq = lin & 15;
        const float4 v = *(const float4*)(W2 + (size_t)k * 64 + nq * 4);
        uint32_t* d = sW2 + k * 68 + nq * 4;
        d[0] = f2tf32(v.x); d[1] = f2tf32(v.y);
        d[2] = f2tf32(v.z); d[3] = f2tf32(v.w);
    }
    __syncthreads();

    // m tile: silu(P1[src] + P2[dst] + dist2*W1r + b1) -> tf32 smem [e][68]
#pragma unroll 4
    for (int it = 0; it < 32; ++it) {
        const int idx = it * 256 + tid;
        const int e = idx >> 6, k = idx & 63;
        float v = g_P[(size_t)sSrc[e] * 128 + k]
                + g_P[(size_t)sDst[e] * 128 + 64 + k]
                + sD2[e] * sW1r[k] + sB1[k];
        sM[e * 68 + k] = f2tf32(silu_f(v));
    }
    __syncthreads();

    // GEMM2 via tf32 mma: each warp handles 16 edges x 64 cols
    float acc[8][4];
#pragma unroll
    for (int j = 0; j < 8; j++)
#pragma unroll
        for (int q = 0; q < 4; q++) acc[j][q] = 0.f;

#pragma unroll
    for (int ks = 0; ks < 8; ks++) {
        const int kb = ks * 8;
        uint32_t af[4], bf[2];
        const int r = warp * 16 + gq;
        af[0] = sM[r * 68 + kb + tq];           af[1] = sM[(r + 8) * 68 + kb + tq];
        af[2] = sM[r * 68 + kb + tq + 4];       af[3] = sM[(r + 8) * 68 + kb + tq + 4];
#pragma unroll
        for (int j = 0; j < 8; j++) {
            const int c = j * 8 + gq;
            bf[0] = sW2[(kb + tq) * 68 + c];
            bf[1] = sW2[(kb + tq + 4) * 68 + c];
            mma_tf32(acc[j], af, bf);
        }
    }

    // epilogue: silu(+b2), scatter to g_dh, and m_x . dir scatter to g_dx
    const int r0 = warp * 16 + gq;       // edge (within block), rows r0 and r0+8
    float part0 = 0.f, part1 = 0.f;
#pragma unroll
    for (int j = 0; j < 8; j++) {
        const int c = j * 8 + tq * 2;
        const float bb0 = sB2[c], bb1 = sB2[c + 1];
        const float px0 = sPx[c], px1 = sPx[c + 1];
        {   // row r0
            const float v0 = silu_f(acc[j][0] + bb0);
            const float v1 = silu_f(acc[j][1] + bb1);
            float* d = &g_dh[(size_t)sSrc[r0] * 64 + c];
            atomicAdd(d + 0, v0);
            atomicAdd(d + 1, v1);
            part0 += v0 * px0 + v1 * px1;
        }
        {   // row r0 + 8
            const float v0 = silu_f(acc[j][2] + bb0);
            const float v1 = silu_f(acc[j][3] + bb1);
            float* d = &g_dh[(size_t)sSrc[r0 + 8] * 64 + c];
            atomicAdd(d + 0, v0);
            atomicAdd(d + 1, v1);
            part1 += v0 * px0 + v1 * px1;
        }
    }
    // reduce m_x across the quad (lanes sharing gq)
    part0 += __shfl_xor_sync(0xffffffffu, part0, 1);
    part0 += __shfl_xor_sync(0xffffffffu, part0, 2);
    part1 += __shfl_xor_sync(0xffffffffu, part1, 1);
    part1 += __shfl_xor_sync(0xffffffffu, part1, 2);
    if (tq == 0) {
        const int n0 = sSrc[r0], n1 = sSrc[r0 + 8];
        atomicAdd(&g_dx[(size_t)n0 * 3 + 0], part0 * sDirx[r0]);
        atomicAdd(&g_dx[(size_t)n0 * 3 + 1], part0 * sDiry[r0]);
        atomicAdd(&g_dx[(size_t)n0 * 3 + 2], part0 * sDirz[r0]);
        atomicAdd(&g_dx[(size_t)n1 * 3 + 0], part1 * sDirx[r0 + 8]);
        atomicAdd(&g_dx[(size_t)n1 * 3 + 1], part1 * sDiry[r0 + 8]);
        atomicAdd(&g_dx[(size_t)n1 * 3 + 2], part1 * sDirz[r0 + 8]);
    }
}

// ---------------- x_new = x + delta_x ----------------
__global__ void xout_kernel(const float* __restrict__ x, float* __restrict__ out) {
    const int i = blockIdx.x * blockDim.x + threadIdx.x;
    if (i < BN * 3) out[i] = x[i] + g_dx[i];
}

// ---------------- launch ----------------
extern "C" void kernel_launch(void* const* d_in, const int* in_sizes, int n_in,
                              void* d_out, int out_size) {
    const float* x   = (const float*)d_in[0];
    const float* h   = (const float*)d_in[1];
    const int*   ei  = (const int*)d_in[2];
    const float* pw1 = (const float*)d_in[3];
    const float* pb1 = (const float*)d_in[4];
    const float* pw2 = (const float*)d_in[5];
    const float* pb2 = (const float*)d_in[6];
    const float* pxw = (const float*)d_in[7];
    const float* hw1 = (const float*)d_in[8];
    const float* hb1 = (const float*)d_in[9];
    const float* hw2 = (const float*)d_in[10];
    const float* hb2 = (const float*)d_in[11];

    float* out   = (float*)d_out;
    float* out_x = out;                      // (B,N,3) flattened first
    float* out_h = out + (size_t)BN * 3;     // then (B,N,128)

    const int EDGE_SMEM = (64 * 68 + 128 * 68) * (int)sizeof(uint32_t);  // 52224 B
    cudaFuncSetAttribute(edge_kernel, cudaFuncAttributeMaxDynamicSharedMemorySize, EDGE_SMEM);

    zero_kernel<<<1024, 256>>>();
    gemm_tc<0, 128><<<BN / 128, 256>>>(h, pw1, nullptr, nullptr);              // g_P
    edge_kernel<<<NE / 128, 256, EDGE_SMEM>>>(x, ei, pw1, pb1, pw2, pb2, pxw); // g_dh, g_dx
    gemm_tc<1, 192><<<BN / 128, 256>>>(h, hw1, hb1, nullptr);                  // g_t
    gemm_tc<2, 128><<<BN / 128, 256>>>(h, hw2, hb2, out_h);                    // h_new
    xout_kernel<<<(BN * 3 + 255) / 256, 256>>>(x, out_x);                      // x_new
}